// round 9
// baseline (speedup 1.0000x reference)
#include <cuda_runtime.h>
#include <math.h>
#include <stdint.h>

// ---------------------------------------------------------------------------
// DeepseekV2MoE: T=1024, H=2048, I=1408, E=16, top4 of 16 (grouped), IS=2816.
// R4: 128x128x8 fp32 SIMT GEMM, 8x8 microtile, reg-double-buffered (1 sync/K-tile),
// silu epilogues split into elementwise kernels (in-place), deterministic routing.
// ---------------------------------------------------------------------------

#define T_TOK 1024
#define HID   2048
#define IMID  1408
#define NEXP  16
#define ISH   2816
#define NGROUP 4
#define TOPK   4
#define ROUTED_SCALING 2.5f

#define BM 128
#define BN 128
#define BKK 8

// ---------------- scratch (device globals; allocation-free) ----------------
__device__ float g_gu  [(size_t)NEXP * T_TOK * (2 * IMID)];  // routed raw gate_up / act (184 MB)
__device__ float g_down[(size_t)NEXP * T_TOK * HID];         // routed down out (134 MB)
__device__ float g_sgu [(size_t)T_TOK * (2 * ISH)];          // shared raw gate_up / act (23 MB)
__device__ int   g_topk_ids[T_TOK * TOPK];
__device__ float g_topk_w  [T_TOK * TOPK];
__device__ int   g_tok [NEXP * T_TOK];
__device__ float g_wt  [NEXP * T_TOK];
__device__ int   g_counts[NEXP];
__device__ int   g_slot[T_TOK * TOPK];

// ---------------------------------------------------------------------------
// K1: router. One block per token, 256 threads.
// ---------------------------------------------------------------------------
__global__ void router_kernel(const float* __restrict__ x,
                              const float* __restrict__ gw,
                              const float* __restrict__ bias)
{
    const int t   = blockIdx.x;
    const int tid = threadIdx.x;
    const int lane = tid & 31;
    const int wid  = tid >> 5;

    float acc[NEXP];
    #pragma unroll
    for (int e = 0; e < NEXP; e++) acc[e] = 0.f;

    const float* xr = x + (size_t)t * HID;
    for (int h = tid; h < HID; h += 256) {
        float xv = xr[h];
        #pragma unroll
        for (int e = 0; e < NEXP; e++)
            acc[e] = fmaf(xv, gw[(size_t)e * HID + h], acc[e]);
    }

    __shared__ float sred[8][NEXP];
    __shared__ float slog[NEXP];
    #pragma unroll
    for (int e = 0; e < NEXP; e++) {
        float v = acc[e];
        #pragma unroll
        for (int o = 16; o > 0; o >>= 1) v += __shfl_down_sync(0xffffffffu, v, o);
        if (lane == 0) sred[wid][e] = v;
    }
    __syncthreads();
    if (tid < NEXP) {
        float s = 0.f;
        #pragma unroll
        for (int w = 0; w < 8; w++) s += sred[w][tid];
        slog[tid] = s;
    }
    __syncthreads();

    if (tid == 0) {
        float sc[NEXP], sb[NEXP];
        #pragma unroll
        for (int e = 0; e < NEXP; e++) {
            sc[e] = 1.f / (1.f + expf(-slog[e]));
            sb[e] = sc[e] + bias[e];
        }
        float gsc[NGROUP];
        #pragma unroll
        for (int g = 0; g < NGROUP; g++) {
            float m1 = -1e30f, m2 = -1e30f;
            #pragma unroll
            for (int j = 0; j < 4; j++) {
                float v = sb[g * 4 + j];
                if (v > m1) { m2 = m1; m1 = v; } else if (v > m2) m2 = v;
            }
            gsc[g] = m1 + m2;
        }
        int bg1 = 0;
        for (int g = 1; g < NGROUP; g++) if (gsc[g] > gsc[bg1]) bg1 = g;
        int bg2 = -1;
        for (int g = 0; g < NGROUP; g++)
            if (g != bg1 && (bg2 < 0 || gsc[g] > gsc[bg2])) bg2 = g;

        bool allowed[NEXP], used[NEXP];
        #pragma unroll
        for (int e = 0; e < NEXP; e++) {
            int g = e >> 2;
            allowed[e] = (g == bg1) || (g == bg2);
            used[e] = false;
        }
        int ids[TOPK];
        #pragma unroll
        for (int k = 0; k < TOPK; k++) {
            float best = -1e30f; int bi = -1;
            for (int e = 0; e < NEXP; e++)
                if (allowed[e] && !used[e] && sb[e] > best) { best = sb[e]; bi = e; }
            ids[k] = bi; used[bi] = true;
        }
        float ws = 0.f;
        #pragma unroll
        for (int k = 0; k < TOPK; k++) ws += sc[ids[k]];
        float inv = 1.f / ws;
        #pragma unroll
        for (int k = 0; k < TOPK; k++) {
            g_topk_ids[t * TOPK + k] = ids[k];
            g_topk_w  [t * TOPK + k] = sc[ids[k]] * inv;
        }
    }
}

// ---------------------------------------------------------------------------
// K2: deterministic per-expert compaction (one block of 1024 threads / expert)
// ---------------------------------------------------------------------------
__global__ void compact_kernel()
{
    const int e = blockIdx.x;
    const int t = threadIdx.x;

    int kf = -1;
    #pragma unroll
    for (int k = 0; k < TOPK; k++)
        if (g_topk_ids[t * TOPK + k] == e) kf = k;
    int flag = (kf >= 0) ? 1 : 0;

    __shared__ int s[T_TOK];
    s[t] = flag;
    __syncthreads();
    for (int off = 1; off < T_TOK; off <<= 1) {
        int v = (t >= off) ? s[t - off] : 0;
        __syncthreads();
        s[t] += v;
        __syncthreads();
    }
    int pos = s[t] - flag;
    if (flag) {
        g_tok[e * T_TOK + pos] = t;
        g_wt [e * T_TOK + pos] = g_topk_w[t * TOPK + kf] * ROUTED_SCALING;
        g_slot[t * TOPK + kf]  = e * T_TOK + pos;
    }
    if (t == T_TOK - 1) g_counts[e] = s[T_TOK - 1];
}

// ---------------------------------------------------------------------------
// Generic 128x128x8 GEMM, 8x8 microtile, register double-buffered smem stages.
// C[r][col0..] = A[row(r)] * B    (A gathered via g_tok when GATHER)
// grid: (N/BN, ceil(capacity/BM), experts); 256 threads.
// ---------------------------------------------------------------------------
template<bool GATHER>
__global__ __launch_bounds__(256, 2)
void gemm_kernel(const float* __restrict__ Abase, size_t aexp, int lda,
                 const float* __restrict__ Bbase, size_t bexp, int N, int K,
                 float* __restrict__ Cbase, size_t cexp, int ldc,
                 int nrows)
{
    const int e = blockIdx.z;
    const int n = (nrows >= 0) ? nrows : g_counts[e];
    const int row0 = blockIdx.y * BM;
    if (row0 >= n) return;
    const int col0 = blockIdx.x * BN;
    const int tid = threadIdx.x;

    const float* A = Abase + aexp * e;
    const float* B = Bbase + bexp * e;
    float*       C = Cbase + cexp * e;

    __shared__ float As[2][BKK][BM];
    __shared__ float Bs[2][BKK][BN];
    __shared__ int   stok[BM];

    if (tid < BM) {
        int r = row0 + tid;
        int g = r;
        if (GATHER) g = (r < n) ? g_tok[e * T_TOK + r] : 0;
        stok[tid] = g;
    }
    __syncthreads();

    const int arow = tid >> 1, ak = (tid & 1) * 4;
    const int brow = tid >> 5, bcol = (tid & 31) * 4;
    const int ty = tid >> 4,  tx = tid & 15;

    const bool aok = (row0 + arow) < n;
    const float* aptr = A + (size_t)stok[arow] * lda + ak;
    const float* bptr = B + (size_t)brow * N + col0 + bcol;

    float acc[8][8];
    #pragma unroll
    for (int i = 0; i < 8; i++)
        #pragma unroll
        for (int j = 0; j < 8; j++) acc[i][j] = 0.f;

    const int KT = K / BKK;

    float4 areg = aok ? __ldg((const float4*)aptr) : make_float4(0.f, 0.f, 0.f, 0.f);
    float4 breg = __ldg((const float4*)bptr);
    As[0][ak + 0][arow] = areg.x; As[0][ak + 1][arow] = areg.y;
    As[0][ak + 2][arow] = areg.z; As[0][ak + 3][arow] = areg.w;
    *(float4*)&Bs[0][brow][bcol] = breg;

    for (int t = 0; t < KT; t++) {
        __syncthreads();
        const int buf = t & 1;
        if (t + 1 < KT) {
            areg = aok ? __ldg((const float4*)(aptr + (size_t)(t + 1) * BKK))
                       : make_float4(0.f, 0.f, 0.f, 0.f);
            breg = __ldg((const float4*)(bptr + (size_t)(t + 1) * BKK * N));
        }
        #pragma unroll
        for (int kk = 0; kk < BKK; kk++) {
            float4 a0 = *(const float4*)&As[buf][kk][ty * 4];
            float4 a1 = *(const float4*)&As[buf][kk][64 + ty * 4];
            float4 b0 = *(const float4*)&Bs[buf][kk][tx * 4];
            float4 b1 = *(const float4*)&Bs[buf][kk][64 + tx * 4];
            float av[8] = {a0.x, a0.y, a0.z, a0.w, a1.x, a1.y, a1.z, a1.w};
            float bv[8] = {b0.x, b0.y, b0.z, b0.w, b1.x, b1.y, b1.z, b1.w};
            #pragma unroll
            for (int i = 0; i < 8; i++)
                #pragma unroll
                for (int j = 0; j < 8; j++)
                    acc[i][j] = fmaf(av[i], bv[j], acc[i][j]);
        }
        if (t + 1 < KT) {
            const int nb = buf ^ 1;
            As[nb][ak + 0][arow] = areg.x; As[nb][ak + 1][arow] = areg.y;
            As[nb][ak + 2][arow] = areg.z; As[nb][ak + 3][arow] = areg.w;
            *(float4*)&Bs[nb][brow][bcol] = breg;
        }
    }

    #pragma unroll
    for (int ih = 0; ih < 2; ih++)
        #pragma unroll
        for (int i = 0; i < 4; i++) {
            int r = row0 + ih * 64 + ty * 4 + i;
            if (r < n) {
                float* cp = C + (size_t)r * ldc + col0;
                int ai = ih * 4 + i;
                *(float4*)&cp[tx * 4]      = make_float4(acc[ai][0], acc[ai][1], acc[ai][2], acc[ai][3]);
                *(float4*)&cp[64 + tx * 4] = make_float4(acc[ai][4], acc[ai][5], acc[ai][6], acc[ai][7]);
            }
        }
}

// ---------------------------------------------------------------------------
// Elementwise activations (in-place on raw gate_up buffers)
// ---------------------------------------------------------------------------
__device__ __forceinline__ float silu_mul(float g, float u) {
    return (g / (1.f + __expf(-g))) * u;
}

__global__ void act_routed_kernel()
{
    const int slot = blockIdx.x;                 // 0 .. NEXP*T_TOK-1
    const int e = slot >> 10, pos = slot & (T_TOK - 1);
    if (pos >= g_counts[e]) return;
    const float w = g_wt[slot];
    float4* row = (float4*)(g_gu + (size_t)slot * (2 * IMID));
    const int nq = IMID / 4;                     // 352
    for (int i = threadIdx.x; i < nq; i += blockDim.x) {
        float4 g = row[i], u = row[i + nq];
        float4 v;
        v.x = silu_mul(g.x, u.x) * w;
        v.y = silu_mul(g.y, u.y) * w;
        v.z = silu_mul(g.z, u.z) * w;
        v.w = silu_mul(g.w, u.w) * w;
        row[i] = v;
    }
}

__global__ void act_shared_kernel()
{
    const int t = blockIdx.x;                    // 0 .. T_TOK-1
    float4* row = (float4*)(g_sgu + (size_t)t * (2 * ISH));
    const int nq = ISH / 4;                      // 704
    for (int i = threadIdx.x; i < nq; i += blockDim.x) {
        float4 g = row[i], u = row[i + nq];
        float4 v;
        v.x = silu_mul(g.x, u.x);
        v.y = silu_mul(g.y, u.y);
        v.z = silu_mul(g.z, u.z);
        v.w = silu_mul(g.w, u.w);
        row[i] = v;
    }
}

// ---------------------------------------------------------------------------
// Final combine: out[t] += sum_k g_down[slot[t][k]]
// ---------------------------------------------------------------------------
__global__ void combine_kernel(float* __restrict__ out)
{
    const int idx = blockIdx.x * blockDim.x + threadIdx.x;  // over T*HID/4
    const int t  = idx >> 9;            // HID/4 = 512 float4 per row
    const int hc = (idx & 511) * 4;

    float4 acc = *reinterpret_cast<const float4*>(out + (size_t)t * HID + hc);
    #pragma unroll
    for (int k = 0; k < TOPK; k++) {
        int s = g_slot[t * TOPK + k];
        float4 v = *reinterpret_cast<const float4*>(g_down + (size_t)s * HID + hc);
        acc.x += v.x; acc.y += v.y; acc.z += v.z; acc.w += v.w;
    }
    *reinterpret_cast<float4*>(out + (size_t)t * HID + hc) = acc;
}

// ---------------------------------------------------------------------------
extern "C" void kernel_launch(void* const* d_in, const int* in_sizes, int n_in,
                              void* d_out, int out_size)
{
    const float* x    = (const float*)d_in[0];  // [1024, 2048]
    const float* gw   = (const float*)d_in[1];  // [16, 2048]
    const float* bias = (const float*)d_in[2];  // [16]
    const float* wgu  = (const float*)d_in[3];  // [16, 2048, 2816]
    const float* wd   = (const float*)d_in[4];  // [16, 1408, 2048]
    const float* sgu  = (const float*)d_in[5];  // [2048, 5632]
    const float* sd   = (const float*)d_in[6];  // [2816, 2048]
    float* out = (float*)d_out;                 // [1024, 2048]

    (void)in_sizes; (void)n_in; (void)out_size;

    router_kernel<<<T_TOK, 256>>>(x, gw, bias);
    compact_kernel<<<NEXP, T_TOK>>>();

    float* gu_ptr = nullptr;  float* down_ptr = nullptr;  float* sgu_ptr = nullptr;
    cudaGetSymbolAddress((void**)&gu_ptr,   g_gu);
    cudaGetSymbolAddress((void**)&down_ptr, g_down);
    cudaGetSymbolAddress((void**)&sgu_ptr,  g_sgu);

    // routed gate_up: C[slot][0..2816) = x[tok] * wgu[e]
    {
        dim3 grid((2 * IMID) / BN, T_TOK / BM, NEXP);   // (22, 8, 16)
        gemm_kernel<true><<<grid, 256>>>(
            x, 0, HID,
            wgu, (size_t)HID * (2 * IMID), 2 * IMID, HID,
            gu_ptr, (size_t)T_TOK * (2 * IMID), 2 * IMID,
            -1);
    }
    // shared gate_up: g_sgu = x * sgu
    {
        dim3 grid((2 * ISH) / BN, T_TOK / BM, 1);       // (44, 8)
        gemm_kernel<false><<<grid, 256>>>(
            x, 0, HID,
            sgu, 0, 2 * ISH, HID,
            sgu_ptr, 0, 2 * ISH,
            T_TOK);
    }

    act_routed_kernel<<<NEXP * T_TOK, 256>>>();
    act_shared_kernel<<<T_TOK, 256>>>();

    // routed down: g_down[slot] = act[slot] * wd[e]   (A = g_gu, lda=2816, K=1408)
    {
        dim3 grid(HID / BN, T_TOK / BM, NEXP);          // (16, 8, 16)
        gemm_kernel<false><<<grid, 256>>>(
            gu_ptr, (size_t)T_TOK * (2 * IMID), 2 * IMID,
            wd, (size_t)IMID * HID, HID, IMID,
            down_ptr, (size_t)T_TOK * HID, HID,
            -1);
    }
    // shared down: out = sact * sd   (A = g_sgu, lda=5632, K=2816)
    {
        dim3 grid(HID / BN, T_TOK / BM, 1);             // (16, 8)
        gemm_kernel<false><<<grid, 256>>>(
            sgu_ptr, 0, 2 * ISH,
            sd, 0, HID, ISH,
            out, 0, HID,
            T_TOK);
    }

    combine_kernel<<<(T_TOK * (HID / 4)) / 256, 256>>>(out);
}

// round 10
// speedup vs baseline: 2.9262x; 2.9262x over previous
#include <cuda_runtime.h>
#include <math.h>
#include <stdint.h>

// ---------------------------------------------------------------------------
// DeepseekV2MoE: T=1024, H=2048, I=1408, E=16, top4 of 16 (grouped), IS=2816.
// R9: TF32 tensor-core GEMM (mma.sync m16n8k8), 128x128x16 tiles, 8 warps,
// reg-double-buffered smem pipeline, conflict-free padded fragment loads.
// Router kept exact fp32. silu/combine elementwise fp32.
// ---------------------------------------------------------------------------

#define T_TOK 1024
#define HID   2048
#define IMID  1408
#define NEXP  16
#define ISH   2816
#define NGROUP 4
#define TOPK   4
#define ROUTED_SCALING 2.5f

#define BM 128
#define BN 128
#define BK 16
#define PADA 20    // As row pitch (floats): conflict-free A frag loads
#define PADB 136   // Bs row pitch (floats): conflict-free B frag loads

// ---------------- scratch (device globals; allocation-free) ----------------
__device__ float g_gu  [(size_t)NEXP * T_TOK * (2 * IMID)];  // routed raw gate_up / act
__device__ float g_down[(size_t)NEXP * T_TOK * HID];         // routed down out
__device__ float g_sgu [(size_t)T_TOK * (2 * ISH)];          // shared raw gate_up / act
__device__ int   g_topk_ids[T_TOK * TOPK];
__device__ float g_topk_w  [T_TOK * TOPK];
__device__ int   g_tok [NEXP * T_TOK];
__device__ float g_wt  [NEXP * T_TOK];
__device__ int   g_counts[NEXP];
__device__ int   g_slot[T_TOK * TOPK];

// ---------------------------------------------------------------------------
// K1: router (exact fp32). One block per token, 256 threads.
// ---------------------------------------------------------------------------
__global__ void router_kernel(const float* __restrict__ x,
                              const float* __restrict__ gw,
                              const float* __restrict__ bias)
{
    const int t   = blockIdx.x;
    const int tid = threadIdx.x;
    const int lane = tid & 31;
    const int wid  = tid >> 5;

    float acc[NEXP];
    #pragma unroll
    for (int e = 0; e < NEXP; e++) acc[e] = 0.f;

    const float* xr = x + (size_t)t * HID;
    for (int h = tid; h < HID; h += 256) {
        float xv = xr[h];
        #pragma unroll
        for (int e = 0; e < NEXP; e++)
            acc[e] = fmaf(xv, gw[(size_t)e * HID + h], acc[e]);
    }

    __shared__ float sred[8][NEXP];
    __shared__ float slog[NEXP];
    #pragma unroll
    for (int e = 0; e < NEXP; e++) {
        float v = acc[e];
        #pragma unroll
        for (int o = 16; o > 0; o >>= 1) v += __shfl_down_sync(0xffffffffu, v, o);
        if (lane == 0) sred[wid][e] = v;
    }
    __syncthreads();
    if (tid < NEXP) {
        float s = 0.f;
        #pragma unroll
        for (int w = 0; w < 8; w++) s += sred[w][tid];
        slog[tid] = s;
    }
    __syncthreads();

    if (tid == 0) {
        float sc[NEXP], sb[NEXP];
        #pragma unroll
        for (int e = 0; e < NEXP; e++) {
            sc[e] = 1.f / (1.f + expf(-slog[e]));
            sb[e] = sc[e] + bias[e];
        }
        float gsc[NGROUP];
        #pragma unroll
        for (int g = 0; g < NGROUP; g++) {
            float m1 = -1e30f, m2 = -1e30f;
            #pragma unroll
            for (int j = 0; j < 4; j++) {
                float v = sb[g * 4 + j];
                if (v > m1) { m2 = m1; m1 = v; } else if (v > m2) m2 = v;
            }
            gsc[g] = m1 + m2;
        }
        int bg1 = 0;
        for (int g = 1; g < NGROUP; g++) if (gsc[g] > gsc[bg1]) bg1 = g;
        int bg2 = -1;
        for (int g = 0; g < NGROUP; g++)
            if (g != bg1 && (bg2 < 0 || gsc[g] > gsc[bg2])) bg2 = g;

        bool allowed[NEXP], used[NEXP];
        #pragma unroll
        for (int e = 0; e < NEXP; e++) {
            int g = e >> 2;
            allowed[e] = (g == bg1) || (g == bg2);
            used[e] = false;
        }
        int ids[TOPK];
        #pragma unroll
        for (int k = 0; k < TOPK; k++) {
            float best = -1e30f; int bi = -1;
            for (int e = 0; e < NEXP; e++)
                if (allowed[e] && !used[e] && sb[e] > best) { best = sb[e]; bi = e; }
            ids[k] = bi; used[bi] = true;
        }
        float ws = 0.f;
        #pragma unroll
        for (int k = 0; k < TOPK; k++) ws += sc[ids[k]];
        float inv = 1.f / ws;
        #pragma unroll
        for (int k = 0; k < TOPK; k++) {
            g_topk_ids[t * TOPK + k] = ids[k];
            g_topk_w  [t * TOPK + k] = sc[ids[k]] * inv;
        }
    }
}

// ---------------------------------------------------------------------------
// K2: deterministic per-expert compaction
// ---------------------------------------------------------------------------
__global__ void compact_kernel()
{
    const int e = blockIdx.x;
    const int t = threadIdx.x;

    int kf = -1;
    #pragma unroll
    for (int k = 0; k < TOPK; k++)
        if (g_topk_ids[t * TOPK + k] == e) kf = k;
    int flag = (kf >= 0) ? 1 : 0;

    __shared__ int s[T_TOK];
    s[t] = flag;
    __syncthreads();
    for (int off = 1; off < T_TOK; off <<= 1) {
        int v = (t >= off) ? s[t - off] : 0;
        __syncthreads();
        s[t] += v;
        __syncthreads();
    }
    int pos = s[t] - flag;
    if (flag) {
        g_tok[e * T_TOK + pos] = t;
        g_wt [e * T_TOK + pos] = g_topk_w[t * TOPK + kf] * ROUTED_SCALING;
        g_slot[t * TOPK + kf]  = e * T_TOK + pos;
    }
    if (t == T_TOK - 1) g_counts[e] = s[T_TOK - 1];
}

// ---------------------------------------------------------------------------
// TF32 helpers
// ---------------------------------------------------------------------------
__device__ __forceinline__ uint32_t f2tf32(float x) {
    uint32_t r;
    asm("cvt.rna.tf32.f32 %0, %1;" : "=r"(r) : "f"(x));
    return r;
}

__device__ __forceinline__ void mma_tf32(float c[4], const uint32_t a[4], const uint32_t b[2]) {
    asm volatile(
        "mma.sync.aligned.m16n8k8.row.col.f32.tf32.tf32.f32 "
        "{%0,%1,%2,%3}, {%4,%5,%6,%7}, {%8,%9}, {%0,%1,%2,%3};\n"
        : "+f"(c[0]), "+f"(c[1]), "+f"(c[2]), "+f"(c[3])
        : "r"(a[0]), "r"(a[1]), "r"(a[2]), "r"(a[3]), "r"(b[0]), "r"(b[1]));
}

// ---------------------------------------------------------------------------
// TF32 tensor-core GEMM: C[r] = A[row(r)] * B, 128x128x16 tile, 256 threads.
// Warp grid 2(m) x 4(n): each warp computes 64x32 via 4x4 m16n8k8 mma tiles.
// A staged [m][PADA], B staged [k][PADB] (both tf32-converted at staging).
// grid: (N/BN, capacity/BM, experts)
// ---------------------------------------------------------------------------
template<bool GATHER>
__global__ __launch_bounds__(256)
void gemm_tf32_kernel(const float* __restrict__ Abase, size_t aexp, int lda,
                      const float* __restrict__ Bbase, size_t bexp, int N, int K,
                      float* __restrict__ Cbase, size_t cexp, int ldc,
                      int nrows)
{
    const int e = blockIdx.z;
    const int n = (nrows >= 0) ? nrows : g_counts[e];
    const int row0 = blockIdx.y * BM;
    if (row0 >= n) return;
    const int col0 = blockIdx.x * BN;
    const int tid  = threadIdx.x;
    const int lane = tid & 31;
    const int wid  = tid >> 5;

    const float* A = Abase + aexp * e;
    const float* B = Bbase + bexp * e;
    float*       C = Cbase + cexp * e;

    __shared__ uint32_t As[2][BM * PADA];
    __shared__ uint32_t Bs[2][BK * PADB];
    __shared__ int stok[BM];

    if (tid < BM) {
        int r = row0 + tid;
        int g = r;
        if (GATHER) g = (r < n) ? g_tok[e * T_TOK + r] : 0;
        stok[tid] = g;
    }
    __syncthreads();

    // ---- loader mapping: 512 float4 each for A (128x16) and B (16x128) ----
    const int am0 = tid >> 2;                 // rows handled: am0, am0+64
    const int akc = (tid & 3) * 4;
    const int am1 = am0 + 64;
    const bool aok0 = (row0 + am0) < n;
    const bool aok1 = (row0 + am1) < n;
    const float* aptr0 = A + (size_t)stok[am0] * lda + akc;
    const float* aptr1 = A + (size_t)stok[am1] * lda + akc;

    const int bk0 = tid >> 5;                 // k rows: bk0, bk0+8
    const int bnc = (tid & 31) * 4;
    const float* bptr0 = B + (size_t)bk0 * N + col0 + bnc;
    const float* bptr1 = B + (size_t)(bk0 + 8) * N + col0 + bnc;

    // ---- warp/fragment mapping ----
    const int warp_m = (wid >> 2) * 64;       // 0 or 64
    const int warp_n = (wid & 3) * 32;        // 0,32,64,96

    float acc[4][4][4];
    #pragma unroll
    for (int mb = 0; mb < 4; mb++)
        #pragma unroll
        for (int nb = 0; nb < 4; nb++)
            #pragma unroll
            for (int r = 0; r < 4; r++) acc[mb][nb][r] = 0.f;

    const int KT = K / BK;

    float4 a0, a1, b0, b1;
    // prologue: load stage 0
    a0 = aok0 ? __ldg((const float4*)aptr0) : make_float4(0.f,0.f,0.f,0.f);
    a1 = aok1 ? __ldg((const float4*)aptr1) : make_float4(0.f,0.f,0.f,0.f);
    b0 = __ldg((const float4*)bptr0);
    b1 = __ldg((const float4*)bptr1);
    {
        uint4 ua0 = make_uint4(f2tf32(a0.x), f2tf32(a0.y), f2tf32(a0.z), f2tf32(a0.w));
        uint4 ua1 = make_uint4(f2tf32(a1.x), f2tf32(a1.y), f2tf32(a1.z), f2tf32(a1.w));
        uint4 ub0 = make_uint4(f2tf32(b0.x), f2tf32(b0.y), f2tf32(b0.z), f2tf32(b0.w));
        uint4 ub1 = make_uint4(f2tf32(b1.x), f2tf32(b1.y), f2tf32(b1.z), f2tf32(b1.w));
        *(uint4*)&As[0][am0 * PADA + akc] = ua0;
        *(uint4*)&As[0][am1 * PADA + akc] = ua1;
        *(uint4*)&Bs[0][bk0 * PADB + bnc] = ub0;
        *(uint4*)&Bs[0][(bk0 + 8) * PADB + bnc] = ub1;
    }

    for (int t = 0; t < KT; t++) {
        __syncthreads();
        const int buf = t & 1;

        if (t + 1 < KT) {
            const int koff = (t + 1) * BK;
            a0 = aok0 ? __ldg((const float4*)(aptr0 + koff)) : make_float4(0.f,0.f,0.f,0.f);
            a1 = aok1 ? __ldg((const float4*)(aptr1 + koff)) : make_float4(0.f,0.f,0.f,0.f);
            b0 = __ldg((const float4*)(bptr0 + (size_t)koff * N));
            b1 = __ldg((const float4*)(bptr1 + (size_t)koff * N));
        }

        #pragma unroll
        for (int ks = 0; ks < 2; ks++) {
            uint32_t af[4][4];
            #pragma unroll
            for (int mb = 0; mb < 4; mb++) {
                const int r0 = warp_m + mb * 16 + (lane >> 2);
                const int c0 = ks * 8 + (lane & 3);
                af[mb][0] = As[buf][ r0      * PADA + c0];
                af[mb][1] = As[buf][(r0 + 8) * PADA + c0];
                af[mb][2] = As[buf][ r0      * PADA + c0 + 4];
                af[mb][3] = As[buf][(r0 + 8) * PADA + c0 + 4];
            }
            uint32_t bf[4][2];
            #pragma unroll
            for (int nb = 0; nb < 4; nb++) {
                const int kr = ks * 8 + (lane & 3);
                const int cc = warp_n + nb * 8 + (lane >> 2);
                bf[nb][0] = Bs[buf][ kr      * PADB + cc];
                bf[nb][1] = Bs[buf][(kr + 4) * PADB + cc];
            }
            #pragma unroll
            for (int mb = 0; mb < 4; mb++)
                #pragma unroll
                for (int nb = 0; nb < 4; nb++)
                    mma_tf32(acc[mb][nb], af[mb], bf[nb]);
        }

        if (t + 1 < KT) {
            const int nb2 = buf ^ 1;
            uint4 ua0 = make_uint4(f2tf32(a0.x), f2tf32(a0.y), f2tf32(a0.z), f2tf32(a0.w));
            uint4 ua1 = make_uint4(f2tf32(a1.x), f2tf32(a1.y), f2tf32(a1.z), f2tf32(a1.w));
            uint4 ub0 = make_uint4(f2tf32(b0.x), f2tf32(b0.y), f2tf32(b0.z), f2tf32(b0.w));
            uint4 ub1 = make_uint4(f2tf32(b1.x), f2tf32(b1.y), f2tf32(b1.z), f2tf32(b1.w));
            *(uint4*)&As[nb2][am0 * PADA + akc] = ua0;
            *(uint4*)&As[nb2][am1 * PADA + akc] = ua1;
            *(uint4*)&Bs[nb2][bk0 * PADB + bnc] = ub0;
            *(uint4*)&Bs[nb2][(bk0 + 8) * PADB + bnc] = ub1;
        }
    }

    // ---- epilogue: C fragment layout c0:(r,2c) c1:(r,2c+1) c2:(r+8,2c) c3:(r+8,2c+1)
    #pragma unroll
    for (int mb = 0; mb < 4; mb++) {
        const int rA = row0 + warp_m + mb * 16 + (lane >> 2);
        const int rB = rA + 8;
        #pragma unroll
        for (int nb = 0; nb < 4; nb++) {
            const int c = col0 + warp_n + nb * 8 + (lane & 3) * 2;
            if (rA < n)
                *(float2*)&C[(size_t)rA * ldc + c] = make_float2(acc[mb][nb][0], acc[mb][nb][1]);
            if (rB < n)
                *(float2*)&C[(size_t)rB * ldc + c] = make_float2(acc[mb][nb][2], acc[mb][nb][3]);
        }
    }
}

// ---------------------------------------------------------------------------
// Elementwise activations (in-place, fp32)
// ---------------------------------------------------------------------------
__device__ __forceinline__ float silu_mul(float g, float u) {
    return (g / (1.f + __expf(-g))) * u;
}

__global__ void act_routed_kernel()
{
    const int slot = blockIdx.x;                 // 0 .. NEXP*T_TOK-1
    const int e = slot >> 10, pos = slot & (T_TOK - 1);
    if (pos >= g_counts[e]) return;
    const float w = g_wt[slot];
    float4* row = (float4*)(g_gu + (size_t)slot * (2 * IMID));
    const int nq = IMID / 4;                     // 352
    for (int i = threadIdx.x; i < nq; i += blockDim.x) {
        float4 g = row[i], u = row[i + nq];
        float4 v;
        v.x = silu_mul(g.x, u.x) * w;
        v.y = silu_mul(g.y, u.y) * w;
        v.z = silu_mul(g.z, u.z) * w;
        v.w = silu_mul(g.w, u.w) * w;
        row[i] = v;
    }
}

__global__ void act_shared_kernel()
{
    const int t = blockIdx.x;                    // 0 .. T_TOK-1
    float4* row = (float4*)(g_sgu + (size_t)t * (2 * ISH));
    const int nq = ISH / 4;                      // 704
    for (int i = threadIdx.x; i < nq; i += blockDim.x) {
        float4 g = row[i], u = row[i + nq];
        float4 v;
        v.x = silu_mul(g.x, u.x);
        v.y = silu_mul(g.y, u.y);
        v.z = silu_mul(g.z, u.z);
        v.w = silu_mul(g.w, u.w);
        row[i] = v;
    }
}

// ---------------------------------------------------------------------------
// Final combine: out[t] += sum_k g_down[slot[t][k]]
// ---------------------------------------------------------------------------
__global__ void combine_kernel(float* __restrict__ out)
{
    const int idx = blockIdx.x * blockDim.x + threadIdx.x;  // over T*HID/4
    const int t  = idx >> 9;
    const int hc = (idx & 511) * 4;

    float4 acc = *reinterpret_cast<const float4*>(out + (size_t)t * HID + hc);
    #pragma unroll
    for (int k = 0; k < TOPK; k++) {
        int s = g_slot[t * TOPK + k];
        float4 v = *reinterpret_cast<const float4*>(g_down + (size_t)s * HID + hc);
        acc.x += v.x; acc.y += v.y; acc.z += v.z; acc.w += v.w;
    }
    *reinterpret_cast<float4*>(out + (size_t)t * HID + hc) = acc;
}

// ---------------------------------------------------------------------------
extern "C" void kernel_launch(void* const* d_in, const int* in_sizes, int n_in,
                              void* d_out, int out_size)
{
    const float* x    = (const float*)d_in[0];  // [1024, 2048]
    const float* gw   = (const float*)d_in[1];  // [16, 2048]
    const float* bias = (const float*)d_in[2];  // [16]
    const float* wgu  = (const float*)d_in[3];  // [16, 2048, 2816]
    const float* wd   = (const float*)d_in[4];  // [16, 1408, 2048]
    const float* sgu  = (const float*)d_in[5];  // [2048, 5632]
    const float* sd   = (const float*)d_in[6];  // [2816, 2048]
    float* out = (float*)d_out;                 // [1024, 2048]

    (void)in_sizes; (void)n_in; (void)out_size;

    router_kernel<<<T_TOK, 256>>>(x, gw, bias);
    compact_kernel<<<NEXP, T_TOK>>>();

    float* gu_ptr = nullptr;  float* down_ptr = nullptr;  float* sgu_ptr = nullptr;
    cudaGetSymbolAddress((void**)&gu_ptr,   g_gu);
    cudaGetSymbolAddress((void**)&down_ptr, g_down);
    cudaGetSymbolAddress((void**)&sgu_ptr,  g_sgu);

    // routed gate_up: g_gu[slot][0..2816) = x[tok] * wgu[e]
    {
        dim3 grid((2 * IMID) / BN, T_TOK / BM, NEXP);   // (22, 8, 16)
        gemm_tf32_kernel<true><<<grid, 256>>>(
            x, 0, HID,
            wgu, (size_t)HID * (2 * IMID), 2 * IMID, HID,
            gu_ptr, (size_t)T_TOK * (2 * IMID), 2 * IMID,
            -1);
    }
    // shared gate_up: g_sgu = x * sgu
    {
        dim3 grid((2 * ISH) / BN, T_TOK / BM, 1);       // (44, 8)
        gemm_tf32_kernel<false><<<grid, 256>>>(
            x, 0, HID,
            sgu, 0, 2 * ISH, HID,
            sgu_ptr, 0, 2 * ISH,
            T_TOK);
    }

    act_routed_kernel<<<NEXP * T_TOK, 256>>>();
    act_shared_kernel<<<T_TOK, 256>>>();

    // routed down: g_down[slot] = act[slot] * wd[e]
    {
        dim3 grid(HID / BN, T_TOK / BM, NEXP);          // (16, 8, 16)
        gemm_tf32_kernel<false><<<grid, 256>>>(
            gu_ptr, (size_t)T_TOK * (2 * IMID), 2 * IMID,
            wd, (size_t)IMID * HID, HID, IMID,
            down_ptr, (size_t)T_TOK * HID, HID,
            -1);
    }
    // shared down: out = sact * sd
    {
        dim3 grid(HID / BN, T_TOK / BM, 1);             // (16, 8)
        gemm_tf32_kernel<false><<<grid, 256>>>(
            sgu_ptr, 0, 2 * ISH,
            sd, 0, HID, ISH,
            out, 0, HID,
            T_TOK);
    }

    combine_kernel<<<(T_TOK * (HID / 4)) / 256, 256>>>(out);
}

// round 12
// speedup vs baseline: 2.9307x; 1.0015x over previous
#include <cuda_runtime.h>
#include <math.h>
#include <stdint.h>

// ---------------------------------------------------------------------------
// DeepseekV2MoE: T=1024, H=2048, I=1408, E=16, top4 of 16 (grouped), IS=2816.
// R12: mma.sync TF32 GEMM (sm_103-safe; no 'a'-suffix features) with a
// 4-stage cp.async multistage pipeline (raw fp32 in smem, cvt.rna at
// fragment load). 128x128x16 tiles, 8 warps x (64x32) warp tiles.
// Router exact fp32; silu/combine fp32 elementwise; deterministic routing.
// ---------------------------------------------------------------------------

#define T_TOK 1024
#define HID   2048
#define IMID  1408
#define NEXP  16
#define ISH   2816
#define NGROUP 4
#define TOPK   4
#define ROUTED_SCALING 2.5f

#define BM 128
#define BN 128
#define BK 16
#define NSTAGE 4
#define PADA 20            // As row pitch (floats)
#define PADB 136           // Bs row pitch (floats)
#define AS_FLOATS (BM * PADA)            // 2560
#define BS_FLOATS (BK * PADB)            // 2176
#define A_TOTAL   (NSTAGE * AS_FLOATS)   // 10240
#define DSM_FLOATS (A_TOTAL + NSTAGE * BS_FLOATS)   // 18944 floats = 75776 B
#define DSM_BYTES (DSM_FLOATS * 4)

// ---------------- scratch (device globals; allocation-free) ----------------
__device__ float g_gu  [(size_t)NEXP * T_TOK * (2 * IMID)];
__device__ float g_down[(size_t)NEXP * T_TOK * HID];
__device__ float g_sgu [(size_t)T_TOK * (2 * ISH)];
__device__ int   g_topk_ids[T_TOK * TOPK];
__device__ float g_topk_w  [T_TOK * TOPK];
__device__ int   g_tok [NEXP * T_TOK];
__device__ float g_wt  [NEXP * T_TOK];
__device__ int   g_counts[NEXP];
__device__ int   g_slot[T_TOK * TOPK];

// ---------------------------------------------------------------------------
// helpers
// ---------------------------------------------------------------------------
__device__ __forceinline__ uint32_t smem_u32(const void* p) {
    uint32_t a;
    asm("{ .reg .u64 t; cvta.to.shared.u64 t, %1; cvt.u32.u64 %0, t; }"
        : "=r"(a) : "l"(p));
    return a;
}

__device__ __forceinline__ uint32_t f2tf32(float x) {
    uint32_t r;
    asm("cvt.rna.tf32.f32 %0, %1;" : "=r"(r) : "f"(x));
    return r;
}

__device__ __forceinline__ void cp_async16(uint32_t dst, const void* src, uint32_t src_sz) {
    asm volatile("cp.async.cg.shared.global [%0], [%1], 16, %2;"
                 :: "r"(dst), "l"(src), "r"(src_sz) : "memory");
}

#define CP_COMMIT() asm volatile("cp.async.commit_group;" ::: "memory")
#define CP_WAIT(n)  asm volatile("cp.async.wait_group %0;" :: "n"(n) : "memory")

__device__ __forceinline__ void mma_tf32(float c[4], const uint32_t a[4], const uint32_t b[2]) {
    asm volatile(
        "mma.sync.aligned.m16n8k8.row.col.f32.tf32.tf32.f32 "
        "{%0,%1,%2,%3}, {%4,%5,%6,%7}, {%8,%9}, {%0,%1,%2,%3};\n"
        : "+f"(c[0]), "+f"(c[1]), "+f"(c[2]), "+f"(c[3])
        : "r"(a[0]), "r"(a[1]), "r"(a[2]), "r"(a[3]), "r"(b[0]), "r"(b[1]));
}

// ---------------------------------------------------------------------------
// K1: router (exact fp32). One block per token, 256 threads.
// ---------------------------------------------------------------------------
__global__ void router_kernel(const float* __restrict__ x,
                              const float* __restrict__ gw,
                              const float* __restrict__ bias)
{
    const int t   = blockIdx.x;
    const int tid = threadIdx.x;
    const int lane = tid & 31;
    const int wid  = tid >> 5;

    float acc[NEXP];
    #pragma unroll
    for (int e = 0; e < NEXP; e++) acc[e] = 0.f;

    const float* xr = x + (size_t)t * HID;
    for (int h = tid; h < HID; h += 256) {
        float xv = xr[h];
        #pragma unroll
        for (int e = 0; e < NEXP; e++)
            acc[e] = fmaf(xv, gw[(size_t)e * HID + h], acc[e]);
    }

    __shared__ float sred[8][NEXP];
    __shared__ float slog[NEXP];
    #pragma unroll
    for (int e = 0; e < NEXP; e++) {
        float v = acc[e];
        #pragma unroll
        for (int o = 16; o > 0; o >>= 1) v += __shfl_down_sync(0xffffffffu, v, o);
        if (lane == 0) sred[wid][e] = v;
    }
    __syncthreads();
    if (tid < NEXP) {
        float s = 0.f;
        #pragma unroll
        for (int w = 0; w < 8; w++) s += sred[w][tid];
        slog[tid] = s;
    }
    __syncthreads();

    if (tid == 0) {
        float sc[NEXP], sb[NEXP];
        #pragma unroll
        for (int e = 0; e < NEXP; e++) {
            sc[e] = 1.f / (1.f + expf(-slog[e]));
            sb[e] = sc[e] + bias[e];
        }
        float gsc[NGROUP];
        #pragma unroll
        for (int g = 0; g < NGROUP; g++) {
            float m1 = -1e30f, m2 = -1e30f;
            #pragma unroll
            for (int j = 0; j < 4; j++) {
                float v = sb[g * 4 + j];
                if (v > m1) { m2 = m1; m1 = v; } else if (v > m2) m2 = v;
            }
            gsc[g] = m1 + m2;
        }
        int bg1 = 0;
        for (int g = 1; g < NGROUP; g++) if (gsc[g] > gsc[bg1]) bg1 = g;
        int bg2 = -1;
        for (int g = 0; g < NGROUP; g++)
            if (g != bg1 && (bg2 < 0 || gsc[g] > gsc[bg2])) bg2 = g;

        bool allowed[NEXP], used[NEXP];
        #pragma unroll
        for (int e = 0; e < NEXP; e++) {
            int g = e >> 2;
            allowed[e] = (g == bg1) || (g == bg2);
            used[e] = false;
        }
        int ids[TOPK];
        #pragma unroll
        for (int k = 0; k < TOPK; k++) {
            float best = -1e30f; int bi = -1;
            for (int e = 0; e < NEXP; e++)
                if (allowed[e] && !used[e] && sb[e] > best) { best = sb[e]; bi = e; }
            ids[k] = bi; used[bi] = true;
        }
        float ws = 0.f;
        #pragma unroll
        for (int k = 0; k < TOPK; k++) ws += sc[ids[k]];
        float inv = 1.f / ws;
        #pragma unroll
        for (int k = 0; k < TOPK; k++) {
            g_topk_ids[t * TOPK + k] = ids[k];
            g_topk_w  [t * TOPK + k] = sc[ids[k]] * inv;
        }
    }
}

// ---------------------------------------------------------------------------
// K2: deterministic per-expert compaction
// ---------------------------------------------------------------------------
__global__ void compact_kernel()
{
    const int e = blockIdx.x;
    const int t = threadIdx.x;

    int kf = -1;
    #pragma unroll
    for (int k = 0; k < TOPK; k++)
        if (g_topk_ids[t * TOPK + k] == e) kf = k;
    int flag = (kf >= 0) ? 1 : 0;

    __shared__ int s[T_TOK];
    s[t] = flag;
    __syncthreads();
    for (int off = 1; off < T_TOK; off <<= 1) {
        int v = (t >= off) ? s[t - off] : 0;
        __syncthreads();
        s[t] += v;
        __syncthreads();
    }
    int pos = s[t] - flag;
    if (flag) {
        g_tok[e * T_TOK + pos] = t;
        g_wt [e * T_TOK + pos] = g_topk_w[t * TOPK + kf] * ROUTED_SCALING;
        g_slot[t * TOPK + kf]  = e * T_TOK + pos;
    }
    if (t == T_TOK - 1) g_counts[e] = s[T_TOK - 1];
}

// ---------------------------------------------------------------------------
// TF32 mma.sync GEMM with 4-stage cp.async pipeline.
// C[r][col0..] = A[row(r)] * B. grid: (N/BN, capacity/BM, experts), 256 thr.
// ---------------------------------------------------------------------------
template<bool GATHER>
__global__ __launch_bounds__(256, 2)
void gemm_tf32_kernel(const float* __restrict__ Abase, size_t aexp, int lda,
                      const float* __restrict__ Bbase, size_t bexp, int N, int K,
                      float* __restrict__ Cbase, size_t cexp, int ldc,
                      int nrows)
{
    const int e = blockIdx.z;
    const int n = (nrows >= 0) ? nrows : g_counts[e];
    const int row0 = blockIdx.y * BM;
    if (row0 >= n) return;
    const int col0 = blockIdx.x * BN;
    const int tid  = threadIdx.x;
    const int lane = tid & 31;
    const int wid  = tid >> 5;

    extern __shared__ float dsm[];
    __shared__ int stok[BM];

    const float* A = Abase + aexp * e;
    const float* B = Bbase + bexp * e;
    float*       C = Cbase + cexp * e;

    if (tid < BM) {
        int r = row0 + tid;
        stok[tid] = GATHER ? ((r < n) ? g_tok[e * T_TOK + r] : 0) : r;
    }
    __syncthreads();

    // ---- staging maps (hoisted; only k0 varies per tile) ----
    // A: 512 chunks of 16B; thread covers chunks tid and tid+256.
    const int rA0 = tid >> 2;            // 0..63
    const int rA1 = rA0 + 64;            // 64..127
    const int kcA = (tid & 3) * 4;       // 0,4,8,12
    const uint32_t szA0 = ((row0 + rA0) < n) ? 16u : 0u;
    const uint32_t szA1 = ((row0 + rA1) < n) ? 16u : 0u;
    const float* aptr0 = A + (size_t)stok[rA0] * lda + kcA;
    const float* aptr1 = A + (size_t)stok[rA1] * lda + kcA;
    // B: 512 chunks; thread covers k-rows krB, krB+8.
    const int krB = tid >> 5;            // 0..7
    const int ncB = (tid & 31) * 4;      // 0..124
    const float* bptr0 = B + (size_t)krB * N + col0 + ncB;
    const float* bptr1 = B + (size_t)(krB + 8) * N + col0 + ncB;

    const uint32_t dsm_u = smem_u32(dsm);
    const uint32_t dA0 = dsm_u + (uint32_t)(rA0 * PADA + kcA) * 4u;
    const uint32_t dA1 = dsm_u + (uint32_t)(rA1 * PADA + kcA) * 4u;
    const uint32_t dB0 = dsm_u + (uint32_t)(A_TOTAL + krB * PADB + ncB) * 4u;
    const uint32_t dB1 = dsm_u + (uint32_t)(A_TOTAL + (krB + 8) * PADB + ncB) * 4u;

    const int KT = K / BK;

    // ---- warp/fragment mapping (identical to R10, verified correct) ----
    const int warp_m = (wid >> 2) * 64;
    const int warp_n = (wid & 3) * 32;

    float acc[4][4][4];
    #pragma unroll
    for (int mb = 0; mb < 4; mb++)
        #pragma unroll
        for (int nb = 0; nb < 4; nb++)
            #pragma unroll
            for (int r = 0; r < 4; r++) acc[mb][nb][r] = 0.f;

    // ---- prologue: stages 0..NSTAGE-2 ----
    #pragma unroll
    for (int s = 0; s < NSTAGE - 1; s++) {
        if (s < KT) {
            const int k0 = s * BK;
            const uint32_t soA = (uint32_t)(s * AS_FLOATS) * 4u;
            const uint32_t soB = (uint32_t)(s * BS_FLOATS) * 4u;
            cp_async16(dA0 + soA, aptr0 + k0, szA0);
            cp_async16(dA1 + soA, aptr1 + k0, szA1);
            cp_async16(dB0 + soB, bptr0 + (size_t)k0 * N, 16u);
            cp_async16(dB1 + soB, bptr1 + (size_t)k0 * N, 16u);
        }
        CP_COMMIT();
    }

    for (int t = 0; t < KT; t++) {
        CP_WAIT(NSTAGE - 2);
        __syncthreads();

        // issue copies for tile t+NSTAGE-1 (buffer (t-1)%NSTAGE: its consumers
        // finished mma(t-1) before the barrier above)
        {
            const int tn = t + NSTAGE - 1;
            if (tn < KT) {
                const int s = tn & (NSTAGE - 1);
                const int k0 = tn * BK;
                const uint32_t soA = (uint32_t)(s * AS_FLOATS) * 4u;
                const uint32_t soB = (uint32_t)(s * BS_FLOATS) * 4u;
                cp_async16(dA0 + soA, aptr0 + k0, szA0);
                cp_async16(dA1 + soA, aptr1 + k0, szA1);
                cp_async16(dB0 + soB, bptr0 + (size_t)k0 * N, 16u);
                cp_async16(dB1 + soB, bptr1 + (size_t)k0 * N, 16u);
            }
            CP_COMMIT();
        }

        // ---- consume tile t ----
        const int s = t & (NSTAGE - 1);
        const float* As = dsm + s * AS_FLOATS;
        const float* Bs = dsm + A_TOTAL + s * BS_FLOATS;

        #pragma unroll
        for (int ks = 0; ks < 2; ks++) {
            uint32_t af[4][4];
            #pragma unroll
            for (int mb = 0; mb < 4; mb++) {
                const int r0 = warp_m + mb * 16 + (lane >> 2);
                const int c0 = ks * 8 + (lane & 3);
                af[mb][0] = f2tf32(As[ r0      * PADA + c0]);
                af[mb][1] = f2tf32(As[(r0 + 8) * PADA + c0]);
                af[mb][2] = f2tf32(As[ r0      * PADA + c0 + 4]);
                af[mb][3] = f2tf32(As[(r0 + 8) * PADA + c0 + 4]);
            }
            uint32_t bf[4][2];
            #pragma unroll
            for (int nb = 0; nb < 4; nb++) {
                const int kr = ks * 8 + (lane & 3);
                const int cc = warp_n + nb * 8 + (lane >> 2);
                bf[nb][0] = f2tf32(Bs[ kr      * PADB + cc]);
                bf[nb][1] = f2tf32(Bs[(kr + 4) * PADB + cc]);
            }
            #pragma unroll
            for (int mb = 0; mb < 4; mb++)
                #pragma unroll
                for (int nb = 0; nb < 4; nb++)
                    mma_tf32(acc[mb][nb], af[mb], bf[nb]);
        }
    }

    // ---- epilogue (identical to R10) ----
    #pragma unroll
    for (int mb = 0; mb < 4; mb++) {
        const int rA = row0 + warp_m + mb * 16 + (lane >> 2);
        const int rB = rA + 8;
        #pragma unroll
        for (int nb = 0; nb < 4; nb++) {
            const int c = col0 + warp_n + nb * 8 + (lane & 3) * 2;
            if (rA < n)
                *(float2*)&C[(size_t)rA * ldc + c] = make_float2(acc[mb][nb][0], acc[mb][nb][1]);
            if (rB < n)
                *(float2*)&C[(size_t)rB * ldc + c] = make_float2(acc[mb][nb][2], acc[mb][nb][3]);
        }
    }
}

// ---------------------------------------------------------------------------
// Elementwise activations (in-place, fp32)
// ---------------------------------------------------------------------------
__device__ __forceinline__ float silu_mul(float g, float u) {
    return (g / (1.f + __expf(-g))) * u;
}

__global__ void act_routed_kernel()
{
    const int slot = blockIdx.x;
    const int e = slot >> 10, pos = slot & (T_TOK - 1);
    if (pos >= g_counts[e]) return;
    const float w = g_wt[slot];
    float4* row = (float4*)(g_gu + (size_t)slot * (2 * IMID));
    const int nq = IMID / 4;
    for (int i = threadIdx.x; i < nq; i += blockDim.x) {
        float4 g = row[i], u = row[i + nq];
        float4 v;
        v.x = silu_mul(g.x, u.x) * w;
        v.y = silu_mul(g.y, u.y) * w;
        v.z = silu_mul(g.z, u.z) * w;
        v.w = silu_mul(g.w, u.w) * w;
        row[i] = v;
    }
}

__global__ void act_shared_kernel()
{
    const int t = blockIdx.x;
    float4* row = (float4*)(g_sgu + (size_t)t * (2 * ISH));
    const int nq = ISH / 4;
    for (int i = threadIdx.x; i < nq; i += blockDim.x) {
        float4 g = row[i], u = row[i + nq];
        float4 v;
        v.x = silu_mul(g.x, u.x);
        v.y = silu_mul(g.y, u.y);
        v.z = silu_mul(g.z, u.z);
        v.w = silu_mul(g.w, u.w);
        row[i] = v;
    }
}

// ---------------------------------------------------------------------------
// Final combine: out[t] += sum_k g_down[slot[t][k]]
// ---------------------------------------------------------------------------
__global__ void combine_kernel(float* __restrict__ out)
{
    const int idx = blockIdx.x * blockDim.x + threadIdx.x;
    const int t  = idx >> 9;
    const int hc = (idx & 511) * 4;

    float4 acc = *reinterpret_cast<const float4*>(out + (size_t)t * HID + hc);
    #pragma unroll
    for (int k = 0; k < TOPK; k++) {
        int s = g_slot[t * TOPK + k];
        float4 v = *reinterpret_cast<const float4*>(g_down + (size_t)s * HID + hc);
        acc.x += v.x; acc.y += v.y; acc.z += v.z; acc.w += v.w;
    }
    *reinterpret_cast<float4*>(out + (size_t)t * HID + hc) = acc;
}

// ---------------------------------------------------------------------------
extern "C" void kernel_launch(void* const* d_in, const int* in_sizes, int n_in,
                              void* d_out, int out_size)
{
    const float* x    = (const float*)d_in[0];  // [1024, 2048]
    const float* gw   = (const float*)d_in[1];  // [16, 2048]
    const float* bias = (const float*)d_in[2];  // [16]
    const float* wgu  = (const float*)d_in[3];  // [16, 2048, 2816]
    const float* wd   = (const float*)d_in[4];  // [16, 1408, 2048]
    const float* sgu  = (const float*)d_in[5];  // [2048, 5632]
    const float* sd   = (const float*)d_in[6];  // [2816, 2048]
    float* out = (float*)d_out;                 // [1024, 2048]

    (void)in_sizes; (void)n_in; (void)out_size;

    static int smem_set = 0;
    if (!smem_set) {
        cudaFuncSetAttribute(gemm_tf32_kernel<true>,
                             cudaFuncAttributeMaxDynamicSharedMemorySize, DSM_BYTES);
        cudaFuncSetAttribute(gemm_tf32_kernel<false>,
                             cudaFuncAttributeMaxDynamicSharedMemorySize, DSM_BYTES);
        smem_set = 1;
    }

    router_kernel<<<T_TOK, 256>>>(x, gw, bias);
    compact_kernel<<<NEXP, T_TOK>>>();

    float* gu_ptr = nullptr;  float* down_ptr = nullptr;  float* sgu_ptr = nullptr;
    cudaGetSymbolAddress((void**)&gu_ptr,   g_gu);
    cudaGetSymbolAddress((void**)&down_ptr, g_down);
    cudaGetSymbolAddress((void**)&sgu_ptr,  g_sgu);

    // routed gate_up: g_gu[slot][0..2816) = x[tok] * wgu[e]
    {
        dim3 grid((2 * IMID) / BN, T_TOK / BM, NEXP);   // (22, 8, 16)
        gemm_tf32_kernel<true><<<grid, 256, DSM_BYTES>>>(
            x, 0, HID,
            wgu, (size_t)HID * (2 * IMID), 2 * IMID, HID,
            gu_ptr, (size_t)T_TOK * (2 * IMID), 2 * IMID,
            -1);
    }
    // shared gate_up: g_sgu = x * sgu
    {
        dim3 grid((2 * ISH) / BN, T_TOK / BM, 1);       // (44, 8)
        gemm_tf32_kernel<false><<<grid, 256, DSM_BYTES>>>(
            x, 0, HID,
            sgu, 0, 2 * ISH, HID,
            sgu_ptr, 0, 2 * ISH,
            T_TOK);
    }

    act_routed_kernel<<<NEXP * T_TOK, 256>>>();
    act_shared_kernel<<<T_TOK, 256>>>();

    // routed down: g_down[slot] = act[slot] * wd[e]
    {
        dim3 grid(HID / BN, T_TOK / BM, NEXP);          // (16, 8, 16)
        gemm_tf32_kernel<false><<<grid, 256, DSM_BYTES>>>(
            gu_ptr, (size_t)T_TOK * (2 * IMID), 2 * IMID,
            wd, (size_t)IMID * HID, HID, IMID,
            down_ptr, (size_t)T_TOK * HID, HID,
            -1);
    }
    // shared down: out = sact * sd
    {
        dim3 grid(HID / BN, T_TOK / BM, 1);             // (16, 8)
        gemm_tf32_kernel<false><<<grid, 256, DSM_BYTES>>>(
            sgu_ptr, 0, 2 * ISH,
            sd, 0, HID, ISH,
            out, 0, HID,
            T_TOK);
    }

    combine_kernel<<<(T_TOK * (HID / 4)) / 256, 256>>>(out);
}